// round 16
// baseline (speedup 1.0000x reference)
#include <cuda_runtime.h>
#include <cuda_fp16.h>
#include <math_constants.h>
#include <cstdint>

// Problem constants
#define D_MODEL 1024
#define N_HEADS 16
#define HEAD_DIM 64
#define BATCH 2
#define SEQ 2048
#define BT (BATCH * SEQ)            // 4096 rows

// ---------------------------------------------------------------------------
// Scratch (device globals; no allocation allowed)
// ---------------------------------------------------------------------------
__device__ __half g_q16[BT * D_MODEL];      // Q after rope, scaled by log2e/8
__device__ __half g_k16[BT * D_MODEL];      // K after rope
__device__ __half g_v16[BT * D_MODEL];      // V
__device__ __half g_ao16[BT * D_MODEL];     // attention output
__device__ __half g_x16[BT * D_MODEL];      // x in fp16
__device__ __half g_wq16[D_MODEL * D_MODEL];
__device__ __half g_wk16[D_MODEL * D_MODEL];
__device__ __half g_wv16[D_MODEL * D_MODEL];
__device__ __half g_wo16[D_MODEL * D_MODEL];
__device__ float2 g_rope[SEQ * 32];         // (cos, sin) per (pos, pair)

// ---------------------------------------------------------------------------
// Helpers
// ---------------------------------------------------------------------------
__device__ __forceinline__ uint32_t smem_to_u32(const void* p) {
    uint32_t a;
    asm("{ .reg .u64 t; cvta.to.shared.u64 t, %1; cvt.u32.u64 %0, t; }"
        : "=r"(a) : "l"(p));
    return a;
}

__device__ __forceinline__ uint32_t pack_h2(float a, float b) {
    __half2 h = __floats2half2_rn(a, b);
    return *(uint32_t*)&h;
}

__device__ __forceinline__ float ex2f(float x) {
    float y;
    asm("ex2.approx.ftz.f32 %0, %1;" : "=f"(y) : "f"(x));
    return y;
}

__device__ __forceinline__ uint32_t ex2_h2(uint32_t x) {
    uint32_t y;
    asm("ex2.approx.f16x2 %0, %1;" : "=r"(y) : "r"(x));
    return y;
}

__device__ __forceinline__ void ldsm_x4(uint32_t addr, uint32_t* r) {
    asm volatile("ldmatrix.sync.aligned.m8n8.x4.shared.b16 {%0,%1,%2,%3}, [%4];"
                 : "=r"(r[0]), "=r"(r[1]), "=r"(r[2]), "=r"(r[3]) : "r"(addr));
}

__device__ __forceinline__ void ldsm_x4_trans(uint32_t addr, uint32_t* r) {
    asm volatile("ldmatrix.sync.aligned.m8n8.x4.trans.shared.b16 {%0,%1,%2,%3}, [%4];"
                 : "=r"(r[0]), "=r"(r[1]), "=r"(r[2]), "=r"(r[3]) : "r"(addr));
}

__device__ __forceinline__ void mma_f16(float* d, const uint32_t* a,
                                        const uint32_t* b) {
    asm volatile(
        "mma.sync.aligned.m16n8k16.row.col.f32.f16.f16.f32 "
        "{%0,%1,%2,%3}, {%4,%5,%6,%7}, {%8,%9}, {%0,%1,%2,%3};"
        : "+f"(d[0]), "+f"(d[1]), "+f"(d[2]), "+f"(d[3])
        : "r"(a[0]), "r"(a[1]), "r"(a[2]), "r"(a[3]), "r"(b[0]), "r"(b[1]));
}

__device__ __forceinline__ void cp_async16(uint32_t dst, const void* src) {
    asm volatile("cp.async.cg.shared.global [%0], [%1], 16;"
                 :: "r"(dst), "l"(src) : "memory");
}

#define CP_COMMIT()  asm volatile("cp.async.commit_group;" ::: "memory")
#define CP_WAIT(N)   asm volatile("cp.async.wait_group %0;" :: "n"(N) : "memory")

#define SWZ(c4, rr) ((((c4) ^ ((rr) & 7)) & 7) << 4)

#define LOG2E 1.4426950408889634f
#define H2_ONES 0x3C003C00u        // (1.0h, 1.0h)

// ---------------------------------------------------------------------------
// RoPE cos/sin table
// ---------------------------------------------------------------------------
__global__ void rope_table_kernel(float2* __restrict__ tab)
{
    int idx = blockIdx.x * blockDim.x + threadIdx.x;   // 65536
    int i   = idx & 31;
    int pos = idx >> 5;
    float ang = (float)pos * powf(10000.0f, -(float)i / 32.0f);
    float s, c;
    sincosf(ang, &s, &c);
    tab[idx] = make_float2(c, s);
}

// ---------------------------------------------------------------------------
// Fused fp32 -> fp16 conversion for x + 4 weights
// ---------------------------------------------------------------------------
__global__ void conv_all_kernel(const float* __restrict__ x,
                                const float* __restrict__ wq,
                                const float* __restrict__ wk,
                                const float* __restrict__ wv,
                                const float* __restrict__ wo,
                                __half* __restrict__ x16,
                                __half* __restrict__ wq16,
                                __half* __restrict__ wk16,
                                __half* __restrict__ wv16,
                                __half* __restrict__ wo16)
{
    const int z = blockIdx.y;
    const float* src = (z == 0) ? x : (z == 1) ? wq : (z == 2) ? wk
                                  : (z == 3) ? wv : wo;
    __half* dst = (z == 0) ? x16 : (z == 1) ? wq16 : (z == 2) ? wk16
                              : (z == 3) ? wv16 : wo16;
    const int n8 = (z == 0) ? (BT * D_MODEL / 8) : (D_MODEL * D_MODEL / 8);
    int i = blockIdx.x * blockDim.x + threadIdx.x;
    if (i >= n8) return;
    float4 v0 = ((const float4*)src)[i * 2];
    float4 v1 = ((const float4*)src)[i * 2 + 1];
    uint4 o;
    o.x = pack_h2(v0.x, v0.y); o.y = pack_h2(v0.z, v0.w);
    o.z = pack_h2(v1.x, v1.y); o.w = pack_h2(v1.z, v1.w);
    ((uint4*)dst)[i] = o;
}

// ---------------------------------------------------------------------------
// fp16 mma.sync GEMM (NT), 3-stage cp.async (unchanged)
// ---------------------------------------------------------------------------
#define G_STAGES 3
#define G_STAGE_BYTES 32768
#define GEMM_SMEM_BYTES (G_STAGES * G_STAGE_BYTES)

__global__ __launch_bounds__(256, 2)
void gemm_f16(const __half* __restrict__ A,
              const __half* __restrict__ B0, const __half* __restrict__ B1,
              const __half* __restrict__ B2,
              void* C0, void* C1, void* C2,
              const float2* __restrict__ rope_tab, int final_proj)
{
    extern __shared__ char smem[];
    const uint32_t sb = smem_to_u32(smem);
    const int tid  = threadIdx.x;
    const int wid  = tid >> 5;
    const int lane = tid & 31;
    const int m0 = blockIdx.y * 128;
    const int n0 = blockIdx.x * 128;
    const int z  = blockIdx.z;
    const __half* B = (z == 0) ? B0 : (z == 1) ? B1 : B2;
    const int warpM0 = (wid & 3) * 32;
    const int warpN0 = (wid >> 2) * 64;

    float acc[2][8][4];
#pragma unroll
    for (int mt = 0; mt < 2; mt++)
#pragma unroll
        for (int nt = 0; nt < 8; nt++)
#pragma unroll
            for (int r = 0; r < 4; r++) acc[mt][nt][r] = 0.f;

    const int lrow = tid >> 3;
    const int lc4  = tid & 7;

    auto produce = [&](int chunk) {
        const int k0 = chunk * 64;
        const uint32_t dst = sb + (chunk % G_STAGES) * G_STAGE_BYTES;
#pragma unroll
        for (int ii = 0; ii < 8; ii++) {
            int row = lrow + (ii & 3) * 32;
            const __half* src = (ii < 4)
                ? &A[(size_t)(m0 + row) * 1024 + k0 + lc4 * 8]
                : &B[(size_t)(n0 + row) * 1024 + k0 + lc4 * 8];
            uint32_t d = dst + ((ii < 4) ? 0u : 16384u) + row * 128 + SWZ(lc4, row);
            cp_async16(d, src);
        }
        CP_COMMIT();
    };

    auto compute = [&](int buf) {
        const uint32_t ab = sb + buf * G_STAGE_BYTES;
        const uint32_t bb = ab + 16384;
#pragma unroll
        for (int s = 0; s < 4; s++) {
            uint32_t afr[2][4];
#pragma unroll
            for (int mt = 0; mt < 2; mt++) {
                int row = warpM0 + mt * 16 + (lane & 7) + ((lane >> 3) & 1) * 8;
                int c4  = s * 2 + (lane >> 4);
                ldsm_x4(ab + row * 128 + SWZ(c4, row), afr[mt]);
            }
            uint32_t bfr[4][4];
#pragma unroll
            for (int p = 0; p < 4; p++) {
                int row = warpN0 + p * 16 + (lane & 7) + ((lane >> 4) & 1) * 8;
                int c4  = s * 2 + ((lane >> 3) & 1);
                ldsm_x4(bb + row * 128 + SWZ(c4, row), bfr[p]);
            }
#pragma unroll
            for (int mt = 0; mt < 2; mt++)
#pragma unroll
                for (int nt = 0; nt < 8; nt++)
                    mma_f16(acc[mt][nt], afr[mt], &bfr[nt >> 1][(nt & 1) * 2]);
        }
    };

    produce(0); produce(1);

    for (int it = 0; it < 16; ++it) {
        CP_WAIT(1);
        __syncthreads();
        if (it + 2 < 16) produce(it + 2);
        compute(it % G_STAGES);
    }

    if (final_proj) {
        float* C = (float*)C0;
#pragma unroll
        for (int mt = 0; mt < 2; mt++)
#pragma unroll
            for (int nt = 0; nt < 8; nt++) {
                int r = m0 + warpM0 + mt * 16 + (lane >> 2);
                int c = n0 + warpN0 + nt * 8 + (lane & 3) * 2;
                *(float2*)&C[(size_t)r * 1024 + c] =
                    make_float2(acc[mt][nt][0], acc[mt][nt][1]);
                *(float2*)&C[(size_t)(r + 8) * 1024 + c] =
                    make_float2(acc[mt][nt][2], acc[mt][nt][3]);
            }
    } else {
        __half* C = (__half*)((z == 0) ? C0 : (z == 1) ? C1 : C2);
        const bool  do_rope = (z < 2);
        const float scale   = (z == 0) ? (0.125f * LOG2E) : 1.0f;
#pragma unroll
        for (int mt = 0; mt < 2; mt++)
#pragma unroll
            for (int nt = 0; nt < 8; nt++) {
                int r = m0 + warpM0 + mt * 16 + (lane >> 2);
                int c = n0 + warpN0 + nt * 8 + (lane & 3) * 2;
                float a0 = acc[mt][nt][0], a1 = acc[mt][nt][1];
                float a2 = acc[mt][nt][2], a3 = acc[mt][nt][3];
                if (do_rope) {
                    int i = (c & 63) >> 1;
                    float2 cs0 = rope_tab[(r & (SEQ - 1)) * 32 + i];
                    float2 cs1 = rope_tab[((r + 8) & (SEQ - 1)) * 32 + i];
                    float b0 = a0 * cs0.x - a1 * cs0.y;
                    float b1 = a0 * cs0.y + a1 * cs0.x;
                    float b2 = a2 * cs1.x - a3 * cs1.y;
                    float b3 = a2 * cs1.y + a3 * cs1.x;
                    a0 = b0 * scale; a1 = b1 * scale;
                    a2 = b2 * scale; a3 = b3 * scale;
                }
                *(uint32_t*)&C[(size_t)r * 1024 + c]       = pack_h2(a0, a1);
                *(uint32_t*)&C[(size_t)(r + 8) * 1024 + c] = pack_h2(a2, a3);
            }
    }
}

// ---------------------------------------------------------------------------
// Flash attention, fp16 mma.sync, causal, base-2 softmax.
// Q-TILE PAIRING (uniform single wave) + 2-STAGE single-barrier KV ring:
//   tile t: CP_WAIT(0) -> __syncthreads -> produce(t+1) into (t-1)'s buffer
//           -> compute(t).  One barrier per tile; produce latency covered
//           by compute(t).
// Register diet (target <=102 regs, 5 CTAs/SM = 20 warps):
//   no Q-fragment hoist (reload via ldsm inside QK loop), inline P fragments.
// SMEM: Q 8KB + 2 x 16KB = 40KB; 5 CTAs/SM.
// ---------------------------------------------------------------------------
#define AT_BQ 64
#define AT_BK 64
#define AT_SMEM (8192 + 2 * 16384)           // 40960
#define NT2 (SEQ / AT_BQ)                    // 32 q-tiles

__global__ __launch_bounds__(128, 5)
void attn_mma(const __half* __restrict__ Q, const __half* __restrict__ K,
              const __half* __restrict__ V, __half* __restrict__ O)
{
    extern __shared__ char smem[];
    const uint32_t sb = smem_to_u32(smem);
    const uint32_t Qb = sb;

    const int tid  = threadIdx.x;
    const int wid  = tid >> 5;
    const int lane = tid & 31;
    const int pi = blockIdx.x;           // pair index 0..NT2/2-1
    const int h  = blockIdx.y;
    const int b  = blockIdx.z;

    const int wrow0 = wid * 16;
    const int lr  = tid >> 1;            // 0..63
    const int lc0 = (tid & 1) * 4;

    const uint32_t onesB[2] = {H2_ONES, H2_ONES};

    auto produce_kv = [&](int t) {
        const int ks = t * AT_BK;
        const uint32_t Kb = sb + 8192 + (t & 1) * 16384;
        const uint32_t Vb = Kb + 8192;
        const __half* ksrc = &K[(size_t)(b * SEQ + ks + lr) * D_MODEL + h * HEAD_DIM];
        const __half* vsrc = &V[(size_t)(b * SEQ + ks + lr) * D_MODEL + h * HEAD_DIM];
#pragma unroll
        for (int i = 0; i < 4; i++) {
            int c4 = lc0 + i;
            cp_async16(Kb + lr * 128 + SWZ(c4, lr), ksrc + c4 * 8);
            cp_async16(Vb + lr * 128 + SWZ(c4, lr), vsrc + c4 * 8);
        }
        CP_COMMIT();
    };

#pragma unroll 1
    for (int ph = 0; ph < 2; ph++) {
        const int qt = (ph == 0) ? (NT2 - 1 - pi) : pi;   // heavy then light
        const int qbase = qt * AT_BQ;
        const int ntiles = qt + 1;

        if (ph) __syncthreads();     // all warps done with previous phase smem

        // ---- prologue: Q + KV tile 0 (one commit group) ----
        {
            const __half* src = &Q[(size_t)(b * SEQ + qbase + lr) * D_MODEL +
                                   h * HEAD_DIM];
#pragma unroll
            for (int i = 0; i < 4; i++) {
                int c4 = lc0 + i;
                cp_async16(Qb + lr * 128 + SWZ(c4, lr), src + c4 * 8);
            }
        }
        produce_kv(0);

        float Oa[8][4];
#pragma unroll
        for (int nt = 0; nt < 8; nt++)
#pragma unroll
            for (int r = 0; r < 4; r++) Oa[nt][r] = 0.f;
        float La[4] = {0.f, 0.f, 0.f, 0.f};
        float m0 = -CUDART_INF_F, m1 = -CUDART_INF_F;

        const int r0g = qbase + wrow0 + (lane >> 2);
        const int r1g = r0g + 8;

        for (int t = 0; t < ntiles; t++) {
            const uint32_t Kb = sb + 8192 + (t & 1) * 16384;
            const uint32_t Vb = Kb + 8192;

            CP_WAIT(0);                  // tile t (and Q on t=0) resident
            __syncthreads();             // publish + all warps done with t-1
            if (t + 1 < ntiles) produce_kv(t + 1);   // overwrites t-1's buffer

            // ---- S = Q K^T (Q frags reloaded per s-step; smem persists) ----
            float Sa[8][4];
#pragma unroll
            for (int nt = 0; nt < 8; nt++)
#pragma unroll
                for (int r = 0; r < 4; r++) Sa[nt][r] = 0.f;

#pragma unroll
            for (int s = 0; s < 4; s++) {
                uint32_t qfr[4];
                {
                    int rr = wrow0 + (lane & 7) + ((lane >> 3) & 1) * 8;
                    int c4 = s * 2 + (lane >> 4);
                    ldsm_x4(Qb + rr * 128 + SWZ(c4, rr), qfr);
                }
                uint32_t bfr[4][4];
#pragma unroll
                for (int p = 0; p < 4; p++) {
                    int rr = p * 16 + (lane & 7) + ((lane >> 4) & 1) * 8;
                    int c4 = s * 2 + ((lane >> 3) & 1);
                    ldsm_x4(Kb + rr * 128 + SWZ(c4, rr), bfr[p]);
                }
#pragma unroll
                for (int nt = 0; nt < 8; nt++)
                    mma_f16(Sa[nt], qfr, &bfr[nt >> 1][(nt & 1) * 2]);
            }

            // ---- causal mask (last tile only) ----
            if (t == ntiles - 1) {
                const int ks = t * AT_BK;
#pragma unroll
                for (int nt = 0; nt < 8; nt++) {
                    int c = ks + nt * 8 + (lane & 3) * 2;
                    if (c     > r0g) Sa[nt][0] = -CUDART_INF_F;
                    if (c + 1 > r0g) Sa[nt][1] = -CUDART_INF_F;
                    if (c     > r1g) Sa[nt][2] = -CUDART_INF_F;
                    if (c + 1 > r1g) Sa[nt][3] = -CUDART_INF_F;
                }
            }

            // ---- running max (packed fp16 reduce) ----
            float mx0 = -CUDART_INF_F, mx1 = -CUDART_INF_F;
#pragma unroll
            for (int nt = 0; nt < 8; nt++) {
                mx0 = fmaxf(mx0, fmaxf(Sa[nt][0], Sa[nt][1]));
                mx1 = fmaxf(mx1, fmaxf(Sa[nt][2], Sa[nt][3]));
            }
            {
                __half2 mx2 = __floats2half2_rn(mx0, mx1);
                uint32_t mxu = *(uint32_t*)&mx2;
                uint32_t o1 = __shfl_xor_sync(0xffffffffu, mxu, 1);
                mx2 = __hmax2(mx2, *(__half2*)&o1);
                mxu = *(uint32_t*)&mx2;
                uint32_t o2 = __shfl_xor_sync(0xffffffffu, mxu, 2);
                mx2 = __hmax2(mx2, *(__half2*)&o2);
                mx0 = __low2float(mx2);
                mx1 = __high2float(mx2);
            }

            float mn0 = fmaxf(m0, mx0), mn1 = fmaxf(m1, mx1);
            float cr0 = ex2f(m0 - mn0), cr1 = ex2f(m1 - mn1);
            m0 = mn0; m1 = mn1;

#pragma unroll
            for (int nt = 0; nt < 8; nt++) {
                Oa[nt][0] *= cr0; Oa[nt][1] *= cr0;
                Oa[nt][2] *= cr1; Oa[nt][3] *= cr1;
            }
            La[0] *= cr0; La[1] *= cr0; La[2] *= cr1; La[3] *= cr1;

            // ---- P = 2^(S-m); l += P*1; O += P*V ----
#pragma unroll
            for (int s = 0; s < 4; s++) {
                uint32_t afr[4];
                afr[0] = ex2_h2(pack_h2(Sa[2*s][0]   - mn0, Sa[2*s][1]   - mn0));
                afr[1] = ex2_h2(pack_h2(Sa[2*s][2]   - mn1, Sa[2*s][3]   - mn1));
                afr[2] = ex2_h2(pack_h2(Sa[2*s+1][0] - mn0, Sa[2*s+1][1] - mn0));
                afr[3] = ex2_h2(pack_h2(Sa[2*s+1][2] - mn1, Sa[2*s+1][3] - mn1));

                mma_f16(La, afr, onesB);

                uint32_t bfr[4][4];
#pragma unroll
                for (int p = 0; p < 4; p++) {
                    int key = s * 16 + (lane & 7) + ((lane >> 3) & 1) * 8;
                    int c4  = p * 2 + ((lane >> 4) & 1);
                    ldsm_x4_trans(Vb + key * 128 + SWZ(c4, key), bfr[p]);
                }
#pragma unroll
                for (int nt = 0; nt < 8; nt++)
                    mma_f16(Oa[nt], afr, &bfr[nt >> 1][(nt & 1) * 2]);
            }
        }

        // ---- epilogue: write fp16 for this q-tile ----
        float inv0 = 1.f / La[0], inv1 = 1.f / La[2];
#pragma unroll
        for (int nt = 0; nt < 8; nt++) {
            int d = nt * 8 + (lane & 3) * 2;
            uint32_t a = pack_h2(Oa[nt][0] * inv0, Oa[nt][1] * inv0);
            uint32_t c = pack_h2(Oa[nt][2] * inv1, Oa[nt][3] * inv1);
            *(uint32_t*)&O[(size_t)(b * SEQ + r0g) * D_MODEL + h * HEAD_DIM + d] = a;
            *(uint32_t*)&O[(size_t)(b * SEQ + r0g + 8) * D_MODEL + h * HEAD_DIM + d] = c;
        }
    }
}

// ---------------------------------------------------------------------------
// Launch
// ---------------------------------------------------------------------------
extern "C" void kernel_launch(void* const* d_in, const int* in_sizes, int n_in,
                              void* d_out, int out_size)
{
    const float* x  = (const float*)d_in[0];
    const float* Wq = (const float*)d_in[2];
    const float* Wk = (const float*)d_in[3];
    const float* Wv = (const float*)d_in[4];
    const float* Wo = (const float*)d_in[5];
    float*       out = (float*)d_out;

    __half *q16, *k16, *v16, *ao16, *x16, *wq16, *wk16, *wv16, *wo16;
    float2* rope_tab;
    cudaGetSymbolAddress((void**)&q16,  g_q16);
    cudaGetSymbolAddress((void**)&k16,  g_k16);
    cudaGetSymbolAddress((void**)&v16,  g_v16);
    cudaGetSymbolAddress((void**)&ao16, g_ao16);
    cudaGetSymbolAddress((void**)&x16,  g_x16);
    cudaGetSymbolAddress((void**)&wq16, g_wq16);
    cudaGetSymbolAddress((void**)&wk16, g_wk16);
    cudaGetSymbolAddress((void**)&wv16, g_wv16);
    cudaGetSymbolAddress((void**)&wo16, g_wo16);
    cudaGetSymbolAddress((void**)&rope_tab, g_rope);

    cudaFuncSetAttribute(gemm_f16, cudaFuncAttributeMaxDynamicSharedMemorySize,
                         GEMM_SMEM_BYTES);
    cudaFuncSetAttribute(attn_mma, cudaFuncAttributeMaxDynamicSharedMemorySize,
                         AT_SMEM);

    // RoPE table + fp16 conversions
    rope_table_kernel<<<SEQ * 32 / 256, 256>>>(rope_tab);
    {
        dim3 cgrid(BT * D_MODEL / 8 / 256, 5);   // (2048, 5)
        conv_all_kernel<<<cgrid, 256>>>(x, Wq, Wk, Wv, Wo,
                                        x16, wq16, wk16, wv16, wo16);
    }

    // Fused QKV projections (rope + scale fused, fp16 out)
    dim3 qkv_grid(D_MODEL / 128, BT / 128, 3);   // (8, 32, 3)
    gemm_f16<<<qkv_grid, 256, GEMM_SMEM_BYTES>>>(
        x16, wq16, wk16, wv16, q16, k16, v16, rope_tab, 0);

    // Attention: paired q-tiles, 2-stage ring, 5 CTAs/SM
    dim3 attn_grid(NT2 / 2, N_HEADS, BATCH);     // (16, 16, 2) = 512 CTAs
    attn_mma<<<attn_grid, 128, AT_SMEM>>>(q16, k16, v16, ao16);

    // Output projection -> fp32 out
    dim3 o_grid(D_MODEL / 128, BT / 128, 1);
    gemm_f16<<<o_grid, 256, GEMM_SMEM_BYTES>>>(
        ao16, wo16, wo16, wo16, out, out, out, rope_tab, 1);
}

// round 17
// speedup vs baseline: 1.0391x; 1.0391x over previous
#include <cuda_runtime.h>
#include <cuda_fp16.h>
#include <math_constants.h>
#include <cstdint>

// Problem constants
#define D_MODEL 1024
#define N_HEADS 16
#define HEAD_DIM 64
#define BATCH 2
#define SEQ 2048
#define BT (BATCH * SEQ)            // 4096 rows

// ---------------------------------------------------------------------------
// Scratch (device globals; no allocation allowed)
// ---------------------------------------------------------------------------
__device__ __half g_q16[BT * D_MODEL];      // Q after rope, scaled by log2e/8
__device__ __half g_k16[BT * D_MODEL];      // K after rope
__device__ __half g_v16[BT * D_MODEL];      // V
__device__ __half g_ao16[BT * D_MODEL];     // attention output
__device__ __half g_x16[BT * D_MODEL];      // x in fp16
__device__ __half g_wq16[D_MODEL * D_MODEL];
__device__ __half g_wk16[D_MODEL * D_MODEL];
__device__ __half g_wv16[D_MODEL * D_MODEL];
__device__ __half g_wo16[D_MODEL * D_MODEL];
__device__ float2 g_rope[SEQ * 32];         // (cos, sin) per (pos, pair)

// ---------------------------------------------------------------------------
// Helpers
// ---------------------------------------------------------------------------
__device__ __forceinline__ uint32_t smem_to_u32(const void* p) {
    uint32_t a;
    asm("{ .reg .u64 t; cvta.to.shared.u64 t, %1; cvt.u32.u64 %0, t; }"
        : "=r"(a) : "l"(p));
    return a;
}

__device__ __forceinline__ uint32_t pack_h2(float a, float b) {
    __half2 h = __floats2half2_rn(a, b);
    return *(uint32_t*)&h;
}

__device__ __forceinline__ float ex2f(float x) {
    float y;
    asm("ex2.approx.ftz.f32 %0, %1;" : "=f"(y) : "f"(x));
    return y;
}

__device__ __forceinline__ uint32_t ex2_h2(uint32_t x) {
    uint32_t y;
    asm("ex2.approx.f16x2 %0, %1;" : "=r"(y) : "r"(x));
    return y;
}

__device__ __forceinline__ void ldsm_x4(uint32_t addr, uint32_t* r) {
    asm volatile("ldmatrix.sync.aligned.m8n8.x4.shared.b16 {%0,%1,%2,%3}, [%4];"
                 : "=r"(r[0]), "=r"(r[1]), "=r"(r[2]), "=r"(r[3]) : "r"(addr));
}

__device__ __forceinline__ void ldsm_x4_trans(uint32_t addr, uint32_t* r) {
    asm volatile("ldmatrix.sync.aligned.m8n8.x4.trans.shared.b16 {%0,%1,%2,%3}, [%4];"
                 : "=r"(r[0]), "=r"(r[1]), "=r"(r[2]), "=r"(r[3]) : "r"(addr));
}

__device__ __forceinline__ void mma_f16(float* d, const uint32_t* a,
                                        const uint32_t* b) {
    asm volatile(
        "mma.sync.aligned.m16n8k16.row.col.f32.f16.f16.f32 "
        "{%0,%1,%2,%3}, {%4,%5,%6,%7}, {%8,%9}, {%0,%1,%2,%3};"
        : "+f"(d[0]), "+f"(d[1]), "+f"(d[2]), "+f"(d[3])
        : "r"(a[0]), "r"(a[1]), "r"(a[2]), "r"(a[3]), "r"(b[0]), "r"(b[1]));
}

__device__ __forceinline__ void cp_async16(uint32_t dst, const void* src) {
    asm volatile("cp.async.cg.shared.global [%0], [%1], 16;"
                 :: "r"(dst), "l"(src) : "memory");
}

#define CP_COMMIT()  asm volatile("cp.async.commit_group;" ::: "memory")
#define CP_WAIT(N)   asm volatile("cp.async.wait_group %0;" :: "n"(N) : "memory")

#define SWZ(c4, rr) ((((c4) ^ ((rr) & 7)) & 7) << 4)

#define LOG2E 1.4426950408889634f
#define H2_ONES 0x3C003C00u        // (1.0h, 1.0h)

// ---------------------------------------------------------------------------
// Fused fp32 -> fp16 conversion for x + 4 weights, plus rope table (z==5)
// ---------------------------------------------------------------------------
__global__ void conv_all_kernel(const float* __restrict__ x,
                                const float* __restrict__ wq,
                                const float* __restrict__ wk,
                                const float* __restrict__ wv,
                                const float* __restrict__ wo,
                                __half* __restrict__ x16,
                                __half* __restrict__ wq16,
                                __half* __restrict__ wk16,
                                __half* __restrict__ wv16,
                                __half* __restrict__ wo16,
                                float2* __restrict__ rope_tab)
{
    const int z = blockIdx.y;
    int i = blockIdx.x * blockDim.x + threadIdx.x;

    if (z == 5) {
        // rope table: tab[pos*32 + j] = (cos, sin) of pos * theta^(-j/32)
        if (i >= SEQ * 32) return;
        int j   = i & 31;
        int pos = i >> 5;
        float ang = (float)pos * powf(10000.0f, -(float)j / 32.0f);
        float s, c;
        sincosf(ang, &s, &c);
        rope_tab[i] = make_float2(c, s);
        return;
    }

    const float* src = (z == 0) ? x : (z == 1) ? wq : (z == 2) ? wk
                                  : (z == 3) ? wv : wo;
    __half* dst = (z == 0) ? x16 : (z == 1) ? wq16 : (z == 2) ? wk16
                              : (z == 3) ? wv16 : wo16;
    const int n8 = (z == 0) ? (BT * D_MODEL / 8) : (D_MODEL * D_MODEL / 8);
    if (i >= n8) return;
    float4 v0 = ((const float4*)src)[i * 2];
    float4 v1 = ((const float4*)src)[i * 2 + 1];
    uint4 o;
    o.x = pack_h2(v0.x, v0.y); o.y = pack_h2(v0.z, v0.w);
    o.z = pack_h2(v1.x, v1.y); o.w = pack_h2(v1.z, v1.w);
    ((uint4*)dst)[i] = o;
}

// ---------------------------------------------------------------------------
// fp16 mma.sync GEMM (NT), 3-stage cp.async (R15 version, unchanged)
// ---------------------------------------------------------------------------
#define G_STAGES 3
#define G_STAGE_BYTES 32768
#define GEMM_SMEM_BYTES (G_STAGES * G_STAGE_BYTES)

__global__ __launch_bounds__(256, 2)
void gemm_f16(const __half* __restrict__ A,
              const __half* __restrict__ B0, const __half* __restrict__ B1,
              const __half* __restrict__ B2,
              void* C0, void* C1, void* C2,
              const float2* __restrict__ rope_tab, int final_proj)
{
    extern __shared__ char smem[];
    const uint32_t sb = smem_to_u32(smem);
    const int tid  = threadIdx.x;
    const int wid  = tid >> 5;
    const int lane = tid & 31;
    const int m0 = blockIdx.y * 128;
    const int n0 = blockIdx.x * 128;
    const int z  = blockIdx.z;
    const __half* B = (z == 0) ? B0 : (z == 1) ? B1 : B2;
    const int warpM0 = (wid & 3) * 32;
    const int warpN0 = (wid >> 2) * 64;

    float acc[2][8][4];
#pragma unroll
    for (int mt = 0; mt < 2; mt++)
#pragma unroll
        for (int nt = 0; nt < 8; nt++)
#pragma unroll
            for (int r = 0; r < 4; r++) acc[mt][nt][r] = 0.f;

    const int lrow = tid >> 3;
    const int lc4  = tid & 7;

    auto produce = [&](int chunk) {
        const int k0 = chunk * 64;
        const uint32_t dst = sb + (chunk % G_STAGES) * G_STAGE_BYTES;
#pragma unroll
        for (int ii = 0; ii < 8; ii++) {
            int row = lrow + (ii & 3) * 32;
            const __half* src = (ii < 4)
                ? &A[(size_t)(m0 + row) * 1024 + k0 + lc4 * 8]
                : &B[(size_t)(n0 + row) * 1024 + k0 + lc4 * 8];
            uint32_t d = dst + ((ii < 4) ? 0u : 16384u) + row * 128 + SWZ(lc4, row);
            cp_async16(d, src);
        }
        CP_COMMIT();
    };

    auto compute = [&](int buf) {
        const uint32_t ab = sb + buf * G_STAGE_BYTES;
        const uint32_t bb = ab + 16384;
#pragma unroll
        for (int s = 0; s < 4; s++) {
            uint32_t afr[2][4];
#pragma unroll
            for (int mt = 0; mt < 2; mt++) {
                int row = warpM0 + mt * 16 + (lane & 7) + ((lane >> 3) & 1) * 8;
                int c4  = s * 2 + (lane >> 4);
                ldsm_x4(ab + row * 128 + SWZ(c4, row), afr[mt]);
            }
            uint32_t bfr[4][4];
#pragma unroll
            for (int p = 0; p < 4; p++) {
                int row = warpN0 + p * 16 + (lane & 7) + ((lane >> 4) & 1) * 8;
                int c4  = s * 2 + ((lane >> 3) & 1);
                ldsm_x4(bb + row * 128 + SWZ(c4, row), bfr[p]);
            }
#pragma unroll
            for (int mt = 0; mt < 2; mt++)
#pragma unroll
                for (int nt = 0; nt < 8; nt++)
                    mma_f16(acc[mt][nt], afr[mt], &bfr[nt >> 1][(nt & 1) * 2]);
        }
    };

    produce(0); produce(1);

    for (int it = 0; it < 16; ++it) {
        CP_WAIT(1);
        __syncthreads();
        if (it + 2 < 16) produce(it + 2);
        compute(it % G_STAGES);
    }

    if (final_proj) {
        float* C = (float*)C0;
#pragma unroll
        for (int mt = 0; mt < 2; mt++)
#pragma unroll
            for (int nt = 0; nt < 8; nt++) {
                int r = m0 + warpM0 + mt * 16 + (lane >> 2);
                int c = n0 + warpN0 + nt * 8 + (lane & 3) * 2;
                *(float2*)&C[(size_t)r * 1024 + c] =
                    make_float2(acc[mt][nt][0], acc[mt][nt][1]);
                *(float2*)&C[(size_t)(r + 8) * 1024 + c] =
                    make_float2(acc[mt][nt][2], acc[mt][nt][3]);
            }
    } else {
        __half* C = (__half*)((z == 0) ? C0 : (z == 1) ? C1 : C2);
        const bool  do_rope = (z < 2);
        const float scale   = (z == 0) ? (0.125f * LOG2E) : 1.0f;
#pragma unroll
        for (int mt = 0; mt < 2; mt++)
#pragma unroll
            for (int nt = 0; nt < 8; nt++) {
                int r = m0 + warpM0 + mt * 16 + (lane >> 2);
                int c = n0 + warpN0 + nt * 8 + (lane & 3) * 2;
                float a0 = acc[mt][nt][0], a1 = acc[mt][nt][1];
                float a2 = acc[mt][nt][2], a3 = acc[mt][nt][3];
                if (do_rope) {
                    int i = (c & 63) >> 1;
                    float2 cs0 = rope_tab[(r & (SEQ - 1)) * 32 + i];
                    float2 cs1 = rope_tab[((r + 8) & (SEQ - 1)) * 32 + i];
                    float b0 = a0 * cs0.x - a1 * cs0.y;
                    float b1 = a0 * cs0.y + a1 * cs0.x;
                    float b2 = a2 * cs1.x - a3 * cs1.y;
                    float b3 = a2 * cs1.y + a3 * cs1.x;
                    a0 = b0 * scale; a1 = b1 * scale;
                    a2 = b2 * scale; a3 = b3 * scale;
                }
                *(uint32_t*)&C[(size_t)r * 1024 + c]       = pack_h2(a0, a1);
                *(uint32_t*)&C[(size_t)(r + 8) * 1024 + c] = pack_h2(a2, a3);
            }
    }
}

// ---------------------------------------------------------------------------
// Flash attention (R15 exact): fp16 mma.sync, causal, base-2 softmax.
// Q-TILE PAIRING: CTA i handles q-tiles (NT-1-i) then (i); uniform wave.
// Per phase: BQ=64, 128 thr, 3-stage KV cp.async ring, Q-fragment hoist,
// packed fp16 max, ex2.f16x2 P, ones-MMA row sum.
// SMEM: Q 8KB + 3 x 16KB = 56KB; 4 CTAs/SM.
// ---------------------------------------------------------------------------
#define AT_BQ 64
#define AT_BK 64
#define AT_STAGES 3
#define AT_SMEM (8192 + AT_STAGES * 16384)   // 57344
#define NT2 (SEQ / AT_BQ)                     // 32 q-tiles

__global__ __launch_bounds__(128, 4)
void attn_mma(const __half* __restrict__ Q, const __half* __restrict__ K,
              const __half* __restrict__ V, __half* __restrict__ O)
{
    extern __shared__ char smem[];
    const uint32_t sb = smem_to_u32(smem);
    const uint32_t Qb = sb;

    const int tid  = threadIdx.x;
    const int wid  = tid >> 5;
    const int lane = tid & 31;
    const int pi = blockIdx.x;           // pair index 0..NT2/2-1
    const int h  = blockIdx.y;
    const int b  = blockIdx.z;

    const int wrow0 = wid * 16;
    const int lr  = tid >> 1;            // 0..63
    const int lc0 = (tid & 1) * 4;

    const uint32_t onesB[2] = {H2_ONES, H2_ONES};

    auto produce_kv = [&](int t) {
        const int ks = t * AT_BK;
        const uint32_t Kb = sb + 8192 + (t % AT_STAGES) * 16384;
        const uint32_t Vb = Kb + 8192;
        const __half* ksrc = &K[(size_t)(b * SEQ + ks + lr) * D_MODEL + h * HEAD_DIM];
        const __half* vsrc = &V[(size_t)(b * SEQ + ks + lr) * D_MODEL + h * HEAD_DIM];
#pragma unroll
        for (int i = 0; i < 4; i++) {
            int c4 = lc0 + i;
            cp_async16(Kb + lr * 128 + SWZ(c4, lr), ksrc + c4 * 8);
            cp_async16(Vb + lr * 128 + SWZ(c4, lr), vsrc + c4 * 8);
        }
        CP_COMMIT();
    };

#pragma unroll 1
    for (int ph = 0; ph < 2; ph++) {
        const int qt = (ph == 0) ? (NT2 - 1 - pi) : pi;   // heavy then light
        const int qbase = qt * AT_BQ;
        const int ntiles = qt + 1;

        if (ph) __syncthreads();     // all warps done with previous phase smem

        // ---- prologue: Q + KV0 (one group), KV1 ----
        {
            const __half* src = &Q[(size_t)(b * SEQ + qbase + lr) * D_MODEL +
                                   h * HEAD_DIM];
#pragma unroll
            for (int i = 0; i < 4; i++) {
                int c4 = lc0 + i;
                cp_async16(Qb + lr * 128 + SWZ(c4, lr), src + c4 * 8);
            }
        }
        produce_kv(0);
        if (ntiles > 1) { produce_kv(1); CP_WAIT(1); } else { CP_WAIT(0); }
        __syncthreads();

        uint32_t qfr[4][4];
#pragma unroll
        for (int s = 0; s < 4; s++) {
            int rr = wrow0 + (lane & 7) + ((lane >> 3) & 1) * 8;
            int c4 = s * 2 + (lane >> 4);
            ldsm_x4(Qb + rr * 128 + SWZ(c4, rr), qfr[s]);
        }

        float Oa[8][4];
#pragma unroll
        for (int nt = 0; nt < 8; nt++)
#pragma unroll
            for (int r = 0; r < 4; r++) Oa[nt][r] = 0.f;
        float La[4] = {0.f, 0.f, 0.f, 0.f};
        float m0 = -CUDART_INF_F, m1 = -CUDART_INF_F;

        const int r0g = qbase + wrow0 + (lane >> 2);
        const int r1g = r0g + 8;

        for (int t = 0; t < ntiles; t++) {
            const uint32_t Kb = sb + 8192 + (t % AT_STAGES) * 16384;
            const uint32_t Vb = Kb + 8192;

            if (t > 0) {
                if (t + 1 < ntiles) { CP_WAIT(1); } else { CP_WAIT(0); }
                __syncthreads();
            }
            if (t + 2 < ntiles) produce_kv(t + 2);

            // ---- S = Q K^T ----
            float Sa[8][4];
#pragma unroll
            for (int nt = 0; nt < 8; nt++)
#pragma unroll
                for (int r = 0; r < 4; r++) Sa[nt][r] = 0.f;

#pragma unroll
            for (int s = 0; s < 4; s++) {
                uint32_t bfr[4][4];
#pragma unroll
                for (int p = 0; p < 4; p++) {
                    int rr = p * 16 + (lane & 7) + ((lane >> 4) & 1) * 8;
                    int c4 = s * 2 + ((lane >> 3) & 1);
                    ldsm_x4(Kb + rr * 128 + SWZ(c4, rr), bfr[p]);
                }
#pragma unroll
                for (int nt = 0; nt < 8; nt++)
                    mma_f16(Sa[nt], qfr[s], &bfr[nt >> 1][(nt & 1) * 2]);
            }

            // ---- causal mask (last tile only) ----
            if (t == ntiles - 1) {
                const int ks = t * AT_BK;
#pragma unroll
                for (int nt = 0; nt < 8; nt++) {
                    int c = ks + nt * 8 + (lane & 3) * 2;
                    if (c     > r0g) Sa[nt][0] = -CUDART_INF_F;
                    if (c + 1 > r0g) Sa[nt][1] = -CUDART_INF_F;
                    if (c     > r1g) Sa[nt][2] = -CUDART_INF_F;
                    if (c + 1 > r1g) Sa[nt][3] = -CUDART_INF_F;
                }
            }

            // ---- running max (packed fp16 reduce) ----
            float mx0 = -CUDART_INF_F, mx1 = -CUDART_INF_F;
#pragma unroll
            for (int nt = 0; nt < 8; nt++) {
                mx0 = fmaxf(mx0, fmaxf(Sa[nt][0], Sa[nt][1]));
                mx1 = fmaxf(mx1, fmaxf(Sa[nt][2], Sa[nt][3]));
            }
            {
                __half2 mx2 = __floats2half2_rn(mx0, mx1);
                uint32_t mxu = *(uint32_t*)&mx2;
                uint32_t o1 = __shfl_xor_sync(0xffffffffu, mxu, 1);
                mx2 = __hmax2(mx2, *(__half2*)&o1);
                mxu = *(uint32_t*)&mx2;
                uint32_t o2 = __shfl_xor_sync(0xffffffffu, mxu, 2);
                mx2 = __hmax2(mx2, *(__half2*)&o2);
                mx0 = __low2float(mx2);
                mx1 = __high2float(mx2);
            }

            float mn0 = fmaxf(m0, mx0), mn1 = fmaxf(m1, mx1);
            float cr0 = ex2f(m0 - mn0), cr1 = ex2f(m1 - mn1);
            m0 = mn0; m1 = mn1;

#pragma unroll
            for (int nt = 0; nt < 8; nt++) {
                Oa[nt][0] *= cr0; Oa[nt][1] *= cr0;
                Oa[nt][2] *= cr1; Oa[nt][3] *= cr1;
            }
            La[0] *= cr0; La[1] *= cr0; La[2] *= cr1; La[3] *= cr1;

            // ---- P = 2^(S-m); l += P*1; O += P*V ----
#pragma unroll
            for (int s = 0; s < 4; s++) {
                uint32_t afr[4];
                afr[0] = ex2_h2(pack_h2(Sa[2*s][0]   - mn0, Sa[2*s][1]   - mn0));
                afr[1] = ex2_h2(pack_h2(Sa[2*s][2]   - mn1, Sa[2*s][3]   - mn1));
                afr[2] = ex2_h2(pack_h2(Sa[2*s+1][0] - mn0, Sa[2*s+1][1] - mn0));
                afr[3] = ex2_h2(pack_h2(Sa[2*s+1][2] - mn1, Sa[2*s+1][3] - mn1));

                mma_f16(La, afr, onesB);

                uint32_t bfr[4][4];
#pragma unroll
                for (int p = 0; p < 4; p++) {
                    int key = s * 16 + (lane & 7) + ((lane >> 3) & 1) * 8;
                    int c4  = p * 2 + ((lane >> 4) & 1);
                    ldsm_x4_trans(Vb + key * 128 + SWZ(c4, key), bfr[p]);
                }
#pragma unroll
                for (int nt = 0; nt < 8; nt++)
                    mma_f16(Oa[nt], afr, &bfr[nt >> 1][(nt & 1) * 2]);
            }
        }

        // ---- epilogue: write fp16 for this q-tile ----
        float inv0 = 1.f / La[0], inv1 = 1.f / La[2];
#pragma unroll
        for (int nt = 0; nt < 8; nt++) {
            int d = nt * 8 + (lane & 3) * 2;
            uint32_t a = pack_h2(Oa[nt][0] * inv0, Oa[nt][1] * inv0);
            uint32_t c = pack_h2(Oa[nt][2] * inv1, Oa[nt][3] * inv1);
            *(uint32_t*)&O[(size_t)(b * SEQ + r0g) * D_MODEL + h * HEAD_DIM + d] = a;
            *(uint32_t*)&O[(size_t)(b * SEQ + r0g + 8) * D_MODEL + h * HEAD_DIM + d] = c;
        }
    }
}

// ---------------------------------------------------------------------------
// Launch
// ---------------------------------------------------------------------------
extern "C" void kernel_launch(void* const* d_in, const int* in_sizes, int n_in,
                              void* d_out, int out_size)
{
    const float* x  = (const float*)d_in[0];
    const float* Wq = (const float*)d_in[2];
    const float* Wk = (const float*)d_in[3];
    const float* Wv = (const float*)d_in[4];
    const float* Wo = (const float*)d_in[5];
    float*       out = (float*)d_out;

    __half *q16, *k16, *v16, *ao16, *x16, *wq16, *wk16, *wv16, *wo16;
    float2* rope_tab;
    cudaGetSymbolAddress((void**)&q16,  g_q16);
    cudaGetSymbolAddress((void**)&k16,  g_k16);
    cudaGetSymbolAddress((void**)&v16,  g_v16);
    cudaGetSymbolAddress((void**)&ao16, g_ao16);
    cudaGetSymbolAddress((void**)&x16,  g_x16);
    cudaGetSymbolAddress((void**)&wq16, g_wq16);
    cudaGetSymbolAddress((void**)&wk16, g_wk16);
    cudaGetSymbolAddress((void**)&wv16, g_wv16);
    cudaGetSymbolAddress((void**)&wo16, g_wo16);
    cudaGetSymbolAddress((void**)&rope_tab, g_rope);

    cudaFuncSetAttribute(gemm_f16, cudaFuncAttributeMaxDynamicSharedMemorySize,
                         GEMM_SMEM_BYTES);
    cudaFuncSetAttribute(attn_mma, cudaFuncAttributeMaxDynamicSharedMemorySize,
                         AT_SMEM);

    // fp16 conversions + rope table, one launch (z = 0..4 conv, z = 5 table)
    {
        dim3 cgrid(BT * D_MODEL / 8 / 256, 6);   // (2048, 6)
        conv_all_kernel<<<cgrid, 256>>>(x, Wq, Wk, Wv, Wo,
                                        x16, wq16, wk16, wv16, wo16, rope_tab);
    }

    // Fused QKV projections (rope + scale fused, fp16 out)
    dim3 qkv_grid(D_MODEL / 128, BT / 128, 3);   // (8, 32, 3)
    gemm_f16<<<qkv_grid, 256, GEMM_SMEM_BYTES>>>(
        x16, wq16, wk16, wv16, q16, k16, v16, rope_tab, 0);

    // Attention: paired q-tiles -> uniform 33-tile CTAs, single wave
    dim3 attn_grid(NT2 / 2, N_HEADS, BATCH);     // (16, 16, 2) = 512 CTAs
    attn_mma<<<attn_grid, 128, AT_SMEM>>>(q16, k16, v16, ao16);

    // Output projection -> fp32 out
    dim3 o_grid(D_MODEL / 128, BT / 128, 1);
    gemm_f16<<<o_grid, 256, GEMM_SMEM_BYTES>>>(
        ao16, wo16, wo16, wo16, out, out, out, rope_tab, 1);
}